// round 4
// baseline (speedup 1.0000x reference)
#include <cuda_runtime.h>
#include <math.h>

// Problem constants
#define CDIM    64
#define NE      2048
#define HW      4096
#define NPIX    65536            // 16 * 4096
#define NELEM   4194304          // NPIX * CDIM

// Output layout: z_q [NELEM], loss, perplexity, indices [NPIX]
#define OFF_LOSS  NELEM
#define OFF_PERP  (NELEM + 1)
#define OFF_IDX   (NELEM + 2)

// Argmax tiling: 64 px per block x full codebook (32 chunks of 64 codes)
#define BP      64
#define CHUNK   64
#define NCH     32
#define THREADS 256
#define GRID_ARG (NPIX / BP)     // 1024

#define ZS_FLOATS (BP * CDIM)        // 4096  (16 KB, z transposed [px][c])
#define EB_FLOATS (CHUNK * CDIM)     // 4096  (16 KB per buffer, [code][c])
#define SMEM_BYTES ((ZS_FLOATS + 2 * EB_FLOATS) * 4)   // 48 KB -> 4 CTAs/SM

#define OUTBLOCKS 4096

__device__ int   g_idx[NPIX];
__device__ int   g_counts[NE];
__device__ float g_partials[OUTBLOCKS];

// ---------------------------------------------------------------------------
// Kernel 1: fused GEMM-argmax, k-pair packed f32x2.
//   zs  [64 px][64 c], 16B groups swizzled: g = (c>>2) ^ (px>>2)  (&15)
//   eb  [64 code][64 c], 8B groups swizzled: g8 = k2 ^ (code>>2)  (&31)
// Thread tile: 4 px (ty) x 4 codes (tx); per 4 dims: 4 LDS.128 (z) +
// 8 LDS.64 (e) + 32 fma.f32x2. Codebook chunks stream in via cp.async
// (double-buffered); z tile transposed once at block start.
// ---------------------------------------------------------------------------
__global__ void __launch_bounds__(THREADS, 4)
vq_argmax(const float* __restrict__ z, const float* __restrict__ cb,
          float* __restrict__ out, int out_size) {
    extern __shared__ float smem[];
    float* zs  = smem;                 // [64][64] swizzled
    float* eb0 = smem + ZS_FLOATS;     // 2 x [64][64] swizzled

    const int tid = threadIdx.x;
    const int tx  = tid & 15;          // code group (4 codes)
    const int ty  = tid >> 4;          // px group (4 px)

    if (blockIdx.x == 0) {             // zero histogram for vq_out
#pragma unroll
        for (int i = 0; i < NE / THREADS; ++i)
            g_counts[i * THREADS + tid] = 0;
    }

    const int pixBase = blockIdx.x * BP;
    const int b       = pixBase >> 12;
    const int hwBase  = pixBase & 4095;
    const float* zimg = z + (size_t)b * CDIM * HW + hwBase;

    const unsigned ebu = (unsigned)__cvta_generic_to_shared(eb0);

    // ---- cp.async prefetch chunks 0 and 1 (8 x 8B per thread per chunk) ----
#pragma unroll
    for (int pc = 0; pc < 2; ++pc) {
        const float* src = cb + (size_t)pc * CHUNK * CDIM;
        const unsigned dstb = ebu + pc * EB_FLOATS * 4;
#pragma unroll
        for (int i = 0; i < 8; ++i) {
            int idx  = i * THREADS + tid;
            int code = idx >> 5, k2 = idx & 31;
            unsigned dst = dstb +
                (unsigned)((code * CDIM + (((k2 ^ (code >> 2)) & 31) * 2)) * 4);
            asm volatile("cp.async.ca.shared.global [%0], [%1], 8;"
                         :: "r"(dst), "l"(src + code * CDIM + k2 * 2));
        }
        asm volatile("cp.async.commit_group;");
    }

    // ---- zs fill: transpose z[c][px] -> zs[px][c] with 16B-group swizzle ----
#pragma unroll
    for (int i = 0; i < 4; ++i) {
        int idx = i * THREADS + tid;        // 1024 float4 items
        int c = idx >> 4, p4 = idx & 15;
        float4 v = ((const float4*)(zimg + (size_t)c * HW))[p4];
        int base = ((((c >> 2) ^ p4) & 15) << 2) + (c & 3);
        zs[(p4 * 4 + 0) * CDIM + base] = v.x;
        zs[(p4 * 4 + 1) * CDIM + base] = v.y;
        zs[(p4 * 4 + 2) * CDIM + base] = v.z;
        zs[(p4 * 4 + 3) * CDIM + base] = v.w;
    }

    float mx[4];
    int   mi[4];
#pragma unroll
    for (int j = 0; j < 4; ++j) { mx[j] = -3.402823e38f; mi[j] = 0; }

    const float* zrow0 = zs + (ty * 4) * CDIM;

    for (int ch = 0; ch < NCH; ++ch) {
        if (ch >= NCH - 1) asm volatile("cp.async.wait_group 0;");
        else               asm volatile("cp.async.wait_group 1;");
        __syncthreads();

        const float* ebc   = eb0 + (ch & 1) * EB_FLOATS;
        const float* erow0 = ebc + (tx * 4) * CDIM;

        unsigned long long acc[4][4];
#pragma unroll
        for (int j = 0; j < 4; ++j)
#pragma unroll
            for (int n = 0; n < 4; ++n) acc[j][n] = 0ull;

#pragma unroll
        for (int kk = 0; kk < 16; ++kk) {       // 4 dims per step
            const int zg = ((kk ^ ty) & 15) << 2;
            const ulonglong2 zpA = *(const ulonglong2*)(zrow0 + zg);
            const ulonglong2 zpB = *(const ulonglong2*)(zrow0 + CDIM + zg);
            const ulonglong2 zpC = *(const ulonglong2*)(zrow0 + 2 * CDIM + zg);
            const ulonglong2 zpD = *(const ulonglong2*)(zrow0 + 3 * CDIM + zg);
            const int e0 = (((2 * kk)     ^ tx) & 31) * 2;
            const int e1 = (((2 * kk + 1) ^ tx) & 31) * 2;
#pragma unroll
            for (int n = 0; n < 4; ++n) {
                const float* er = erow0 + n * CDIM;
                const unsigned long long eh0 = *(const unsigned long long*)(er + e0);
                const unsigned long long eh1 = *(const unsigned long long*)(er + e1);
                asm("fma.rn.f32x2 %0, %1, %2, %0;" : "+l"(acc[0][n]) : "l"(zpA.x), "l"(eh0));
                asm("fma.rn.f32x2 %0, %1, %2, %0;" : "+l"(acc[0][n]) : "l"(zpA.y), "l"(eh1));
                asm("fma.rn.f32x2 %0, %1, %2, %0;" : "+l"(acc[1][n]) : "l"(zpB.x), "l"(eh0));
                asm("fma.rn.f32x2 %0, %1, %2, %0;" : "+l"(acc[1][n]) : "l"(zpB.y), "l"(eh1));
                asm("fma.rn.f32x2 %0, %1, %2, %0;" : "+l"(acc[2][n]) : "l"(zpC.x), "l"(eh0));
                asm("fma.rn.f32x2 %0, %1, %2, %0;" : "+l"(acc[2][n]) : "l"(zpC.y), "l"(eh1));
                asm("fma.rn.f32x2 %0, %1, %2, %0;" : "+l"(acc[3][n]) : "l"(zpD.x), "l"(eh0));
                asm("fma.rn.f32x2 %0, %1, %2, %0;" : "+l"(acc[3][n]) : "l"(zpD.y), "l"(eh1));
            }
        }

        __syncthreads();                       // everyone done reading buffer
        if (ch + 2 < NCH) {                    // refill this buffer
            const float* src = cb + (size_t)(ch + 2) * CHUNK * CDIM;
            const unsigned dstb = ebu + (ch & 1) * EB_FLOATS * 4;
#pragma unroll
            for (int i = 0; i < 8; ++i) {
                int idx  = i * THREADS + tid;
                int code = idx >> 5, k2 = idx & 31;
                unsigned dst = dstb +
                    (unsigned)((code * CDIM + (((k2 ^ (code >> 2)) & 31) * 2)) * 4);
                asm volatile("cp.async.ca.shared.global [%0], [%1], 8;"
                             :: "r"(dst), "l"(src + code * CDIM + k2 * 2));
            }
            asm volatile("cp.async.commit_group;");
        }

        // fold chunk winners: ascending code order, strict > -> lowest index
        const int cBase = ch * CHUNK + tx * 4;
#pragma unroll
        for (int j = 0; j < 4; ++j) {
#pragma unroll
            for (int n = 0; n < 4; ++n) {
                unsigned lo, hi;
                asm("mov.b64 {%0, %1}, %2;" : "=r"(lo), "=r"(hi) : "l"(acc[j][n]));
                float s = __uint_as_float(lo) + __uint_as_float(hi);
                if (s > mx[j]) { mx[j] = s; mi[j] = cBase + n; }
            }
        }
    }

    // ---- reduce across the 16 code-group lanes ----
#pragma unroll
    for (int off = 8; off; off >>= 1) {
#pragma unroll
        for (int j = 0; j < 4; ++j) {
            float om = __shfl_xor_sync(0xFFFFFFFFu, mx[j], off);
            int   oi = __shfl_xor_sync(0xFFFFFFFFu, mi[j], off);
            if (om > mx[j] || (om == mx[j] && oi < mi[j])) { mx[j] = om; mi[j] = oi; }
        }
    }

    if (tx == 0) {
        const int p0 = pixBase + ty * 4;
#pragma unroll
        for (int j = 0; j < 4; ++j) {
            g_idx[p0 + j] = mi[j];
            int o = OFF_IDX + p0 + j;
            if (o < out_size) out[o] = (float)mi[j];
        }
    }
}

// ---------------------------------------------------------------------------
// Kernel 2: z_q gather + straight-through output + MSE partials + histogram.
// ---------------------------------------------------------------------------
__global__ void __launch_bounds__(256)
vq_out(const float* __restrict__ z, const float* __restrict__ cb,
       float* __restrict__ out) {
    const int t = blockIdx.x * 256 + threadIdx.x;   // float4 index
    const int e = t * 4;
    const int c  = (e >> 12) & 63;
    const int b  = e >> 18;
    const int hw = e & 4095;
    const int p  = (b << 12) + hw;

    const float4 zv = *(const float4*)(z + e);
    const int4  iv  = *(const int4*)(g_idx + p);

    const float q0 = cb[iv.x * CDIM + c];
    const float q1 = cb[iv.y * CDIM + c];
    const float q2 = cb[iv.z * CDIM + c];
    const float q3 = cb[iv.w * CDIM + c];

    float4 ov;
    ov.x = zv.x + (q0 - zv.x);
    ov.y = zv.y + (q1 - zv.y);
    ov.z = zv.z + (q2 - zv.z);
    ov.w = zv.w + (q3 - zv.w);
    *(float4*)(out + e) = ov;

    if (c == 0) {
        atomicAdd(&g_counts[iv.x], 1);
        atomicAdd(&g_counts[iv.y], 1);
        atomicAdd(&g_counts[iv.z], 1);
        atomicAdd(&g_counts[iv.w], 1);
    }

    const float d0 = q0 - zv.x, d1 = q1 - zv.y, d2 = q2 - zv.z, d3 = q3 - zv.w;
    float s = d0 * d0 + d1 * d1 + d2 * d2 + d3 * d3;

    __shared__ float red[256];
    red[threadIdx.x] = s;
    __syncthreads();
#pragma unroll
    for (int off = 128; off; off >>= 1) {
        if (threadIdx.x < off) red[threadIdx.x] += red[threadIdx.x + off];
        __syncthreads();
    }
    if (threadIdx.x == 0) g_partials[blockIdx.x] = red[0];
}

// ---------------------------------------------------------------------------
// Kernel 3: deterministic finalize — loss and perplexity (1024 threads).
// ---------------------------------------------------------------------------
__global__ void vq_fin(float* __restrict__ out, int out_size) {
    __shared__ float red[1024];
    const int t = threadIdx.x;

    float s = 0.0f;
#pragma unroll
    for (int i = 0; i < OUTBLOCKS / 1024; ++i) s += g_partials[i * 1024 + t];
    red[t] = s;
    __syncthreads();
#pragma unroll
    for (int off = 512; off; off >>= 1) {
        if (t < off) red[t] += red[t + off];
        __syncthreads();
    }
    if (t == 0 && OFF_LOSS < out_size)
        out[OFF_LOSS] = 1.25f * red[0] * (1.0f / (float)NELEM);
    __syncthreads();

    float h = 0.0f;
#pragma unroll
    for (int i = 0; i < NE / 1024; ++i) {
        float em = (float)g_counts[i * 1024 + t] * (1.0f / (float)NPIX);
        h += em * logf(em + 1e-10f);
    }
    red[t] = h;
    __syncthreads();
#pragma unroll
    for (int off = 512; off; off >>= 1) {
        if (t < off) red[t] += red[t + off];
        __syncthreads();
    }
    if (t == 0 && OFF_PERP < out_size)
        out[OFF_PERP] = expf(-red[0]);
}

// ---------------------------------------------------------------------------
extern "C" void kernel_launch(void* const* d_in, const int* in_sizes, int n_in,
                              void* d_out, int out_size) {
    const float* z  = (const float*)d_in[0];
    const float* cb = (const float*)d_in[1];
    float* out = (float*)d_out;

    cudaFuncSetAttribute(vq_argmax, cudaFuncAttributeMaxDynamicSharedMemorySize,
                         SMEM_BYTES);

    vq_argmax<<<GRID_ARG, THREADS, SMEM_BYTES>>>(z, cb, out, out_size);
    vq_out<<<OUTBLOCKS, 256>>>(z, cb, out);
    vq_fin<<<1, 1024>>>(out, out_size);
}